// round 10
// baseline (speedup 1.0000x reference)
#include <cuda_runtime.h>
#include <math.h>

#define NB 8
#define NM 64
#define NN 64
#define ND 256
#define NH 8
#define NR (NB*NM*NN)   // 32768 rows

// Scratch
__device__ float g_QA[9][(size_t)NR * ND];   // 0..7: Q-proj per head, 8: V = x@v
__device__ float g_Zp[2][(size_t)NR * ND];   // per-mode partial Z
__device__ float g_A[8][ND * ND];            // A_h = q_h @ k^T
__device__ float g_ow[NH * ND];              // ow[h,d] = sum_v o[h,d,v]

// ---------------------------------------------------------------------------
// packed f32x2 helpers (sm_100+): 2 MACs per fma-pipe issue slot
__device__ __forceinline__ unsigned long long ffma2(unsigned long long a,
                                                    unsigned long long b,
                                                    unsigned long long c) {
    unsigned long long d;
    asm("fma.rn.f32x2 %0, %1, %2, %3;" : "=l"(d) : "l"(a), "l"(b), "l"(c));
    return d;
}
__device__ __forceinline__ unsigned long long bcast2(float a) {
    unsigned long long d;
    asm("mov.b64 %0, {%1, %1};" : "=l"(d) : "f"(a));
    return d;
}
__device__ __forceinline__ float2 unpack2(unsigned long long a) {
    float2 f;
    asm("mov.b64 {%0, %1}, %2;" : "=f"(f.x), "=f"(f.y) : "l"(a));
    return f;
}
__device__ __forceinline__ void cp16(float* dst_smem, const float* src) {
    unsigned s = (unsigned)__cvta_generic_to_shared(dst_smem);
    asm volatile("cp.async.cg.shared.global [%0], [%1], 16;" :: "r"(s), "l"(src));
}

// ---------------------------------------------------------------------------
__global__ void prep_ow_kernel(const float* __restrict__ o) {
    int h = blockIdx.x;
    int d = threadIdx.x;
    const float* row = o + ((size_t)h * ND + d) * ND;
    float s = 0.f;
    #pragma unroll 8
    for (int v = 0; v < ND; v++) s += row[v];
    g_ow[h * ND + d] = s;
}

// ---------------------------------------------------------------------------
// A_h[d][e] = sum_k q[h][d][k] * kmat[e][k]
__global__ void __launch_bounds__(256) prep_A_kernel(const float* __restrict__ q,
                                                     const float* __restrict__ kmat) {
    __shared__ float Qs[64 * 68];
    __shared__ float Ks[64 * 68];
    int h  = blockIdx.z;
    int d0 = blockIdx.y * 64;
    int e0 = blockIdx.x * 64;
    int tid = threadIdx.x, ty = tid >> 4, tx = tid & 15;
    const float* qh = q + (size_t)h * ND * ND;
    unsigned long long acc[4][4];
    #pragma unroll
    for (int i = 0; i < 4; i++)
        #pragma unroll
        for (int j = 0; j < 4; j++) acc[i][j] = 0ull;
    for (int kc = 0; kc < ND; kc += 64) {
        __syncthreads();
        #pragma unroll
        for (int i = tid; i < 64 * 16; i += 256) {
            int r = i >> 4, c = (i & 15) * 4;
            *(float4*)&Qs[r * 68 + c] = *(const float4*)(qh   + (size_t)(d0 + r) * ND + kc + c);
            *(float4*)&Ks[r * 68 + c] = *(const float4*)(kmat + (size_t)(e0 + r) * ND + kc + c);
        }
        __syncthreads();
        for (int kk = 0; kk < 64; kk += 4) {
            ulonglong2 a[4], b[4];
            #pragma unroll
            for (int i = 0; i < 4; i++)
                a[i] = *(const ulonglong2*)&Qs[(ty + 16 * i) * 68 + kk];
            #pragma unroll
            for (int j = 0; j < 4; j++)
                b[j] = *(const ulonglong2*)&Ks[(tx + 16 * j) * 68 + kk];
            #pragma unroll
            for (int i = 0; i < 4; i++)
                #pragma unroll
                for (int j = 0; j < 4; j++) {
                    acc[i][j] = ffma2(a[i].x, b[j].x, acc[i][j]);
                    acc[i][j] = ffma2(a[i].y, b[j].y, acc[i][j]);
                }
        }
    }
    #pragma unroll
    for (int i = 0; i < 4; i++)
        #pragma unroll
        for (int j = 0; j < 4; j++) {
            float2 f = unpack2(acc[i][j]);
            g_A[h][(size_t)(d0 + ty + 16 * i) * ND + e0 + tx + 16 * j] = f.x + f.y;
        }
}

// ---------------------------------------------------------------------------
// For hz<8: g_QA[hz] = X @ g_A[hz]; hz==8: g_QA[8] = X @ v
// 128-row M-tile, 512 threads (16 warps = 4/SMSP), 4x16 per-thread tile,
// double-buffered cp.async over 8 k-chunks of 32. Same smem layout as r6.
__global__ void __launch_bounds__(512, 1) gemm_xw_kernel(const float* __restrict__ x,
                                                         const float* __restrict__ vin) {
    extern __shared__ float smg[];
    float* Xs0 = smg;
    float* Xs1 = smg + 4608;
    float* Ws0 = smg + 9216;
    float* Ws1 = smg + 9216 + 8320;

    int hz = blockIdx.x;
    const float* W = (hz < 8) ? g_A[hz] : vin;
    float* C = g_QA[hz];
    size_t r0 = (size_t)blockIdx.y * 128;
    int tid = threadIdx.x;
    int ty = tid >> 4;      // 0..31  (row group: rows ty + 32*i)
    int tx = tid & 15;      // 0..15  (col group: cols tx*4 + 64*j)

    unsigned long long acc[4][8];
    #pragma unroll
    for (int i = 0; i < 4; i++)
        #pragma unroll
        for (int j = 0; j < 8; j++) acc[i][j] = 0ull;

    #pragma unroll
    for (int i = tid; i < 128 * 8; i += 512) {
        int r = i >> 3, c = (i & 7) * 4;
        cp16(&Xs0[r * 36 + c], x + (r0 + r) * ND + c);
    }
    #pragma unroll
    for (int i = tid; i < 32 * 64; i += 512) {
        int r = i >> 6, c = (i & 63) * 4;
        cp16(&Ws0[r * 260 + c], W + (size_t)r * ND + c);
    }
    asm volatile("cp.async.commit_group;");

    for (int ch = 0; ch < 8; ch++) {
        if (ch + 1 < 8) {
            int dc = (ch + 1) * 32;
            float* Xd = (ch + 1) & 1 ? Xs1 : Xs0;
            float* Wd = (ch + 1) & 1 ? Ws1 : Ws0;
            #pragma unroll
            for (int i = tid; i < 128 * 8; i += 512) {
                int r = i >> 3, c = (i & 7) * 4;
                cp16(&Xd[r * 36 + c], x + (r0 + r) * ND + dc + c);
            }
            #pragma unroll
            for (int i = tid; i < 32 * 64; i += 512) {
                int r = i >> 6, c = (i & 63) * 4;
                cp16(&Wd[r * 260 + c], W + (size_t)(dc + r) * ND + c);
            }
            asm volatile("cp.async.commit_group;");
            asm volatile("cp.async.wait_group 1;");
        } else {
            asm volatile("cp.async.wait_group 0;");
        }
        __syncthreads();

        const float* Xs = (ch & 1) ? Xs1 : Xs0;
        const float* Ws = (ch & 1) ? Ws1 : Ws0;
        #pragma unroll 2
        for (int kk = 0; kk < 32; kk += 4) {
            float a4[4][4];
            #pragma unroll
            for (int i = 0; i < 4; i++)
                *(float4*)a4[i] = *(const float4*)&Xs[(ty + 32 * i) * 36 + kk];
            #pragma unroll
            for (int q = 0; q < 4; q++) {
                unsigned long long b2[8];
                #pragma unroll
                for (int j = 0; j < 4; j++) {
                    ulonglong2 t = *(const ulonglong2*)&Ws[(kk + q) * 260 + tx * 4 + 64 * j];
                    b2[2 * j] = t.x; b2[2 * j + 1] = t.y;
                }
                #pragma unroll
                for (int i = 0; i < 4; i++) {
                    unsigned long long ab = bcast2(a4[i][q]);
                    #pragma unroll
                    for (int j = 0; j < 8; j++)
                        acc[i][j] = ffma2(ab, b2[j], acc[i][j]);
                }
            }
        }
        __syncthreads();
    }

    #pragma unroll
    for (int i = 0; i < 4; i++) {
        size_t row = r0 + ty + 32 * i;
        #pragma unroll
        for (int j = 0; j < 4; j++) {
            float2 lo = unpack2(acc[i][2 * j]);
            float2 hi = unpack2(acc[i][2 * j + 1]);
            *(float4*)(C + row * ND + tx * 4 + 64 * j) = make_float4(lo.x, lo.y, hi.x, hi.y);
        }
    }
}

// ---------------------------------------------------------------------------
// Fused attention + output projection, cp.async-pipelined QA staging.
// QA arrives in k-half panels (64 rows x 128 k): Qb0 = k[0,128), Qb1 = k[128,256).
// Logits accumulate across both phases; K tile loaded ONCE per k (2 B/MAC).
//   mode 0: attn over m (panel p = n), heads 0..3.
//   mode 1: attn over n (panel p = m), heads 4..7.   (round-9 proven)
__global__ void __launch_bounds__(256, 1) attn_kernel(const float* __restrict__ x) {
    extern __shared__ float sm[];
    float* Ks  = sm;                        // 64 x 260 = 16640
    float* Vs  = sm + 16640;                // 64 x 260 = 16640
    float* Qb0 = sm + 2 * 16640;            // 64 x 132 = 8448  (k-half 0)
    float* Qb1 = sm + 2 * 16640 + 8448;     // 64 x 132 = 8448  (k-half 1)
    float* Ss  = sm + 2 * 16640 + 2 * 8448; // 64 x 68  = 4352
    float* ows = Ss + 4352;                 // 4 x 256  = 1024

    int mode = blockIdx.x >> 9;
    int idx  = blockIdx.x & 511;
    int b = idx >> 6;
    int p = idx & 63;
    int tid = threadIdx.x, ty = tid >> 4, tx = tid & 15;
    size_t base = (size_t)b * NM * NN;
    const float* Vg = g_QA[8];
    int h0 = mode ? 4 : 0;

    #define PROW(r) (base + (mode ? ((size_t)p * 64 + (r)) : ((size_t)(r) * 64 + p)))

    // group 0: K, V, ows
    for (int i = tid; i < 64 * 64; i += 256) {
        int r = i >> 6, c = (i & 63) * 4;
        cp16(&Ks[r * 260 + c], x + PROW(r) * ND + c);
    }
    for (int i = tid; i < 64 * 64; i += 256) {
        int r = i >> 6, c = (i & 63) * 4;
        cp16(&Vs[r * 260 + c], Vg + PROW(r) * ND + c);
    }
    {
        int hh = tid >> 6, c = (tid & 63) * 4;
        cp16(&ows[hh * 256 + c], g_ow + (h0 + hh) * ND + c);
    }
    asm volatile("cp.async.commit_group;");
    // group 1: head h0 k-half 0 -> Qb0
    for (int i = tid; i < 64 * 32; i += 256) {
        int r = i >> 5, c = (i & 31) * 4;
        cp16(&Qb0[r * 132 + c], g_QA[h0] + PROW(r) * ND + c);
    }
    asm volatile("cp.async.commit_group;");
    // group 2: head h0 k-half 1 -> Qb1
    for (int i = tid; i < 64 * 32; i += 256) {
        int r = i >> 5, c = (i & 31) * 4;
        cp16(&Qb1[r * 132 + c], g_QA[h0] + PROW(r) * ND + 128 + c);
    }
    asm volatile("cp.async.commit_group;");

    unsigned long long zacc[4][8];
    #pragma unroll
    for (int i = 0; i < 4; i++)
        #pragma unroll
        for (int j = 0; j < 8; j++) zacc[i][j] = 0ull;

    for (int t = 0; t < 4; t++) {
        int h = h0 + t;
        unsigned long long acc[4][4];
        #pragma unroll
        for (int i = 0; i < 4; i++)
            #pragma unroll
            for (int j = 0; j < 4; j++) acc[i][j] = 0ull;

        // ---- phase 0: k in [0,128) from Qb0 ----
        asm volatile("cp.async.wait_group 1;");   // Qb0 (and K/V at t=0) ready
        __syncthreads();
        for (int kk = 0; kk < 128; kk += 4) {
            ulonglong2 a[4], bb[4];
            #pragma unroll
            for (int i = 0; i < 4; i++)
                a[i]  = *(const ulonglong2*)&Qb0[(ty + 16 * i) * 132 + kk];
            #pragma unroll
            for (int j = 0; j < 4; j++)
                bb[j] = *(const ulonglong2*)&Ks[(tx + 16 * j) * 260 + kk];
            #pragma unroll
            for (int i = 0; i < 4; i++)
                #pragma unroll
                for (int j = 0; j < 4; j++) {
                    acc[i][j] = ffma2(a[i].x, bb[j].x, acc[i][j]);
                    acc[i][j] = ffma2(a[i].y, bb[j].y, acc[i][j]);
                }
        }
        __syncthreads();   // all threads done with Qb0
        if (t < 3) {       // prefetch head h+1 k-half 0 -> Qb0
            const float* Qn = g_QA[h + 1];
            for (int i = tid; i < 64 * 32; i += 256) {
                int r = i >> 5, c = (i & 31) * 4;
                cp16(&Qb0[r * 132 + c], Qn + PROW(r) * ND + c);
            }
            asm volatile("cp.async.commit_group;");
        }

        // ---- phase 1: k in [128,256) from Qb1 ----
        if (t == 3) asm volatile("cp.async.wait_group 0;");
        else        asm volatile("cp.async.wait_group 1;");
        __syncthreads();
        for (int kk = 0; kk < 128; kk += 4) {
            ulonglong2 a[4], bb[4];
            #pragma unroll
            for (int i = 0; i < 4; i++)
                a[i]  = *(const ulonglong2*)&Qb1[(ty + 16 * i) * 132 + kk];
            #pragma unroll
            for (int j = 0; j < 4; j++)
                bb[j] = *(const ulonglong2*)&Ks[(tx + 16 * j) * 260 + 128 + kk];
            #pragma unroll
            for (int i = 0; i < 4; i++)
                #pragma unroll
                for (int j = 0; j < 4; j++) {
                    acc[i][j] = ffma2(a[i].x, bb[j].x, acc[i][j]);
                    acc[i][j] = ffma2(a[i].y, bb[j].y, acc[i][j]);
                }
        }
        #pragma unroll
        for (int i = 0; i < 4; i++)
            #pragma unroll
            for (int j = 0; j < 4; j++) {
                float2 f = unpack2(acc[i][j]);
                Ss[(ty + 16 * i) * 68 + tx + 16 * j] = f.x + f.y;
            }
        __syncthreads();   // Qb1 free; Ss visible
        if (t < 3) {       // prefetch head h+1 k-half 1 -> Qb1
            const float* Qn = g_QA[h + 1];
            for (int i = tid; i < 64 * 32; i += 256) {
                int r = i >> 5, c = (i & 31) * 4;
                cp16(&Qb1[r * 132 + c], Qn + PROW(r) * ND + 128 + c);
            }
            asm volatile("cp.async.commit_group;");
        }

        // ---- softmax over z (row-wise), 8 warps x 8 rows ----
        {
            int lane = tid & 31, w = tid >> 5;
            #pragma unroll
            for (int rr = 0; rr < 8; rr++) {
                int row = w * 8 + rr;
                float v0 = Ss[row * 68 + lane];
                float v1 = Ss[row * 68 + lane + 32];
                float m = fmaxf(v0, v1);
                #pragma unroll
                for (int off = 16; off > 0; off >>= 1)
                    m = fmaxf(m, __shfl_xor_sync(0xffffffffu, m, off));
                float e0 = __expf(v0 - m), e1 = __expf(v1 - m);
                float s = e0 + e1;
                #pragma unroll
                for (int off = 16; off > 0; off >>= 1)
                    s += __shfl_xor_sync(0xffffffffu, s, off);
                float inv = 1.0f / s;
                Ss[row * 68 + lane]      = e0 * inv;
                Ss[row * 68 + lane + 32] = e1 * inv;
            }
        }
        __syncthreads();

        // ---- O-phase: 4 rows x 16 cols, folded into zacc with ow_h ----
        unsigned long long oacc[4][8];
        #pragma unroll
        for (int i = 0; i < 4; i++)
            #pragma unroll
            for (int j = 0; j < 8; j++) oacc[i][j] = 0ull;
        #pragma unroll 4
        for (int z = 0; z < 64; z++) {
            unsigned long long b2[8];
            #pragma unroll
            for (int j = 0; j < 4; j++) {
                ulonglong2 tv = *(const ulonglong2*)&Vs[z * 260 + tx * 4 + 64 * j];
                b2[2 * j] = tv.x; b2[2 * j + 1] = tv.y;
            }
            #pragma unroll
            for (int i = 0; i < 4; i++) {
                unsigned long long ab = bcast2(Ss[(ty + 16 * i) * 68 + z]);
                #pragma unroll
                for (int j = 0; j < 8; j++)
                    oacc[i][j] = ffma2(ab, b2[j], oacc[i][j]);
            }
        }
        #pragma unroll
        for (int j = 0; j < 4; j++) {
            ulonglong2 w2 = *(const ulonglong2*)&ows[t * 256 + tx * 4 + 64 * j];
            #pragma unroll
            for (int i = 0; i < 4; i++) {
                zacc[i][2 * j]     = ffma2(oacc[i][2 * j],     w2.x, zacc[i][2 * j]);
                zacc[i][2 * j + 1] = ffma2(oacc[i][2 * j + 1], w2.y, zacc[i][2 * j + 1]);
            }
        }
    }

    float* Zp = g_Zp[mode];
    #pragma unroll
    for (int i = 0; i < 4; i++) {
        int r = ty + 16 * i;
        size_t row = PROW(r);
        #pragma unroll
        for (int j = 0; j < 4; j++) {
            float2 lo = unpack2(zacc[i][2 * j]);
            float2 hi = unpack2(zacc[i][2 * j + 1]);
            *(float4*)(Zp + row * ND + tx * 4 + 64 * j) = make_float4(lo.x, lo.y, hi.x, hi.y);
        }
    }
    #undef PROW
}

// ---------------------------------------------------------------------------
// out = Zp0 + Zp1 (pure streaming add)
__global__ void zfinal_kernel(float* __restrict__ out) {
    size_t i = ((size_t)blockIdx.x * 256 + threadIdx.x) * 4;
    float4 a = *(const float4*)(g_Zp[0] + i);
    float4 b = *(const float4*)(g_Zp[1] + i);
    *(float4*)(out + i) = make_float4(a.x + b.x, a.y + b.y, a.z + b.z, a.w + b.w);
}

// ---------------------------------------------------------------------------
extern "C" void kernel_launch(void* const* d_in, const int* in_sizes, int n_in,
                              void* d_out, int out_size) {
    const float* x  = (const float*)d_in[0];
    const float* q  = (const float*)d_in[1];
    const float* km = (const float*)d_in[2];
    const float* v  = (const float*)d_in[3];
    const float* o  = (const float*)d_in[4];
    float* out = (float*)d_out;

    const size_t attn_smem =
        (size_t)(2 * 16640 + 2 * 8448 + 4352 + 1024) * sizeof(float); // 223616 B
    cudaFuncSetAttribute(attn_kernel, cudaFuncAttributeMaxDynamicSharedMemorySize,
                         (int)attn_smem);
    const size_t gemm_smem = (size_t)(2 * 4608 + 2 * 8320) * sizeof(float); // 103424 B
    cudaFuncSetAttribute(gemm_xw_kernel, cudaFuncAttributeMaxDynamicSharedMemorySize,
                         (int)gemm_smem);

    prep_ow_kernel<<<NH, ND>>>(o);
    prep_A_kernel<<<dim3(4, 4, 8), 256>>>(q, km);
    gemm_xw_kernel<<<dim3(9, NR / 128), 512, gemm_smem>>>(x, v);
    attn_kernel<<<2 * NB * NN, 256, attn_smem>>>(x);
    zfinal_kernel<<<(NR * ND) / (256 * 4), 256>>>(out);
}

// round 11
// speedup vs baseline: 1.0537x; 1.0537x over previous
#include <cuda_runtime.h>
#include <math.h>

#define NB 8
#define NM 64
#define NN 64
#define ND 256
#define NH 8
#define NR (NB*NM*NN)   // 32768 rows

// Scratch
__device__ float g_QA[9][(size_t)NR * ND];   // 0..7: Q-proj per head, 8: V = x@v
__device__ float g_Zp[2][(size_t)NR * ND];   // per-mode partial Z
__device__ float g_A[8][ND * ND];            // A_h = q_h @ k^T
__device__ float g_ow[NH * ND];              // ow[h,d] = sum_v o[h,d,v]

// ---------------------------------------------------------------------------
// packed f32x2 helpers (sm_100+): 2 MACs per fma-pipe issue slot
__device__ __forceinline__ unsigned long long ffma2(unsigned long long a,
                                                    unsigned long long b,
                                                    unsigned long long c) {
    unsigned long long d;
    asm("fma.rn.f32x2 %0, %1, %2, %3;" : "=l"(d) : "l"(a), "l"(b), "l"(c));
    return d;
}
__device__ __forceinline__ unsigned long long bcast2(float a) {
    unsigned long long d;
    asm("mov.b64 %0, {%1, %1};" : "=l"(d) : "f"(a));
    return d;
}
__device__ __forceinline__ float2 unpack2(unsigned long long a) {
    float2 f;
    asm("mov.b64 {%0, %1}, %2;" : "=f"(f.x), "=f"(f.y) : "l"(a));
    return f;
}
__device__ __forceinline__ void cp16(float* dst_smem, const float* src) {
    unsigned s = (unsigned)__cvta_generic_to_shared(dst_smem);
    asm volatile("cp.async.cg.shared.global [%0], [%1], 16;" :: "r"(s), "l"(src));
}

// ---------------------------------------------------------------------------
__global__ void prep_ow_kernel(const float* __restrict__ o) {
    int h = blockIdx.x;
    int d = threadIdx.x;
    const float* row = o + ((size_t)h * ND + d) * ND;
    float s = 0.f;
    #pragma unroll 8
    for (int v = 0; v < ND; v++) s += row[v];
    g_ow[h * ND + d] = s;
}

// ---------------------------------------------------------------------------
// A_h[d][e] = sum_k q[h][d][k] * kmat[e][k]
__global__ void __launch_bounds__(256) prep_A_kernel(const float* __restrict__ q,
                                                     const float* __restrict__ kmat) {
    __shared__ float Qs[64 * 68];
    __shared__ float Ks[64 * 68];
    int h  = blockIdx.z;
    int d0 = blockIdx.y * 64;
    int e0 = blockIdx.x * 64;
    int tid = threadIdx.x, ty = tid >> 4, tx = tid & 15;
    const float* qh = q + (size_t)h * ND * ND;
    unsigned long long acc[4][4];
    #pragma unroll
    for (int i = 0; i < 4; i++)
        #pragma unroll
        for (int j = 0; j < 4; j++) acc[i][j] = 0ull;
    for (int kc = 0; kc < ND; kc += 64) {
        __syncthreads();
        #pragma unroll
        for (int i = tid; i < 64 * 16; i += 256) {
            int r = i >> 4, c = (i & 15) * 4;
            *(float4*)&Qs[r * 68 + c] = *(const float4*)(qh   + (size_t)(d0 + r) * ND + kc + c);
            *(float4*)&Ks[r * 68 + c] = *(const float4*)(kmat + (size_t)(e0 + r) * ND + kc + c);
        }
        __syncthreads();
        for (int kk = 0; kk < 64; kk += 4) {
            ulonglong2 a[4], b[4];
            #pragma unroll
            for (int i = 0; i < 4; i++)
                a[i] = *(const ulonglong2*)&Qs[(ty + 16 * i) * 68 + kk];
            #pragma unroll
            for (int j = 0; j < 4; j++)
                b[j] = *(const ulonglong2*)&Ks[(tx + 16 * j) * 68 + kk];
            #pragma unroll
            for (int i = 0; i < 4; i++)
                #pragma unroll
                for (int j = 0; j < 4; j++) {
                    acc[i][j] = ffma2(a[i].x, b[j].x, acc[i][j]);
                    acc[i][j] = ffma2(a[i].y, b[j].y, acc[i][j]);
                }
        }
    }
    #pragma unroll
    for (int i = 0; i < 4; i++)
        #pragma unroll
        for (int j = 0; j < 4; j++) {
            float2 f = unpack2(acc[i][j]);
            g_A[h][(size_t)(d0 + ty + 16 * i) * ND + e0 + tx + 16 * j] = f.x + f.y;
        }
}

// ---------------------------------------------------------------------------
// For hz<8: g_QA[hz] = X @ g_A[hz]; hz==8: g_QA[8] = X @ v
// 128-row M-tile, 256 threads, 8x16 per-thread tile (0.75 B/MAC).
// X panel staged ONCE at full k (128 x 260); W double-buffered per 32-k chunk.
__global__ void __launch_bounds__(256, 1) gemm_xw_kernel(const float* __restrict__ x,
                                                         const float* __restrict__ vin) {
    extern __shared__ float smg[];
    float* Xs  = smg;                     // 128 x 260 = 33280 floats
    float* Ws0 = smg + 33280;             // 32 x 260  = 8320
    float* Ws1 = smg + 33280 + 8320;      // 32 x 260  = 8320

    int hz = blockIdx.x;
    const float* W = (hz < 8) ? g_A[hz] : vin;
    float* C = g_QA[hz];
    size_t r0 = (size_t)blockIdx.y * 128;
    int tid = threadIdx.x, ty = tid >> 4, tx = tid & 15;   // ty 0..15, tx 0..15

    unsigned long long acc[8][8];
    #pragma unroll
    for (int i = 0; i < 8; i++)
        #pragma unroll
        for (int j = 0; j < 8; j++) acc[i][j] = 0ull;

    // group 0: full X panel + W chunk 0
    for (int i = tid; i < 128 * 64; i += 256) {
        int r = i >> 6, c = (i & 63) * 4;
        cp16(&Xs[r * 260 + c], x + (r0 + r) * ND + c);
    }
    #pragma unroll
    for (int i = tid; i < 32 * 64; i += 256) {
        int r = i >> 6, c = (i & 63) * 4;
        cp16(&Ws0[r * 260 + c], W + (size_t)r * ND + c);
    }
    asm volatile("cp.async.commit_group;");

    for (int ch = 0; ch < 8; ch++) {
        if (ch + 1 < 8) {
            int dc = (ch + 1) * 32;
            float* Wd = (ch + 1) & 1 ? Ws1 : Ws0;
            #pragma unroll
            for (int i = tid; i < 32 * 64; i += 256) {
                int r = i >> 6, c = (i & 63) * 4;
                cp16(&Wd[r * 260 + c], W + (size_t)(dc + r) * ND + c);
            }
            asm volatile("cp.async.commit_group;");
            asm volatile("cp.async.wait_group 1;");
        } else {
            asm volatile("cp.async.wait_group 0;");
        }
        __syncthreads();

        const float* Ws = (ch & 1) ? Ws1 : Ws0;
        int base = ch * 32;
        #pragma unroll 4
        for (int kk = 0; kk < 32; kk += 4) {
            float a4[8][4];
            #pragma unroll
            for (int i = 0; i < 8; i++)
                *(float4*)a4[i] = *(const float4*)&Xs[(ty + 16 * i) * 260 + base + kk];
            #pragma unroll
            for (int q = 0; q < 4; q++) {
                unsigned long long b2[8];
                #pragma unroll
                for (int j = 0; j < 4; j++) {
                    ulonglong2 t = *(const ulonglong2*)&Ws[(kk + q) * 260 + tx * 4 + 64 * j];
                    b2[2 * j] = t.x; b2[2 * j + 1] = t.y;
                }
                #pragma unroll
                for (int i = 0; i < 8; i++) {
                    unsigned long long ab = bcast2(a4[i][q]);
                    #pragma unroll
                    for (int j = 0; j < 8; j++)
                        acc[i][j] = ffma2(ab, b2[j], acc[i][j]);
                }
            }
        }
        __syncthreads();   // done with this W buffer before it's refilled
    }

    #pragma unroll
    for (int i = 0; i < 8; i++) {
        size_t row = r0 + ty + 16 * i;
        #pragma unroll
        for (int j = 0; j < 4; j++) {
            float2 lo = unpack2(acc[i][2 * j]);
            float2 hi = unpack2(acc[i][2 * j + 1]);
            *(float4*)(C + row * ND + tx * 4 + 64 * j) = make_float4(lo.x, lo.y, hi.x, hi.y);
        }
    }
}

// ---------------------------------------------------------------------------
// Fused attention + output projection, cp.async-pipelined QA staging.
// QA arrives in k-half panels (64 rows x 128 k): Qb0 = k[0,128), Qb1 = k[128,256).
// Logits accumulate across both phases; K tile loaded ONCE per k (2 B/MAC).
//   mode 0: attn over m (panel p = n), heads 0..3.
//   mode 1: attn over n (panel p = m), heads 4..7.   (round-9 proven)
__global__ void __launch_bounds__(256, 1) attn_kernel(const float* __restrict__ x) {
    extern __shared__ float sm[];
    float* Ks  = sm;                        // 64 x 260 = 16640
    float* Vs  = sm + 16640;                // 64 x 260 = 16640
    float* Qb0 = sm + 2 * 16640;            // 64 x 132 = 8448  (k-half 0)
    float* Qb1 = sm + 2 * 16640 + 8448;     // 64 x 132 = 8448  (k-half 1)
    float* Ss  = sm + 2 * 16640 + 2 * 8448; // 64 x 68  = 4352
    float* ows = Ss + 4352;                 // 4 x 256  = 1024

    int mode = blockIdx.x >> 9;
    int idx  = blockIdx.x & 511;
    int b = idx >> 6;
    int p = idx & 63;
    int tid = threadIdx.x, ty = tid >> 4, tx = tid & 15;
    size_t base = (size_t)b * NM * NN;
    const float* Vg = g_QA[8];
    int h0 = mode ? 4 : 0;

    #define PROW(r) (base + (mode ? ((size_t)p * 64 + (r)) : ((size_t)(r) * 64 + p)))

    // group 0: K, V, ows
    for (int i = tid; i < 64 * 64; i += 256) {
        int r = i >> 6, c = (i & 63) * 4;
        cp16(&Ks[r * 260 + c], x + PROW(r) * ND + c);
    }
    for (int i = tid; i < 64 * 64; i += 256) {
        int r = i >> 6, c = (i & 63) * 4;
        cp16(&Vs[r * 260 + c], Vg + PROW(r) * ND + c);
    }
    {
        int hh = tid >> 6, c = (tid & 63) * 4;
        cp16(&ows[hh * 256 + c], g_ow + (h0 + hh) * ND + c);
    }
    asm volatile("cp.async.commit_group;");
    // group 1: head h0 k-half 0 -> Qb0
    for (int i = tid; i < 64 * 32; i += 256) {
        int r = i >> 5, c = (i & 31) * 4;
        cp16(&Qb0[r * 132 + c], g_QA[h0] + PROW(r) * ND + c);
    }
    asm volatile("cp.async.commit_group;");
    // group 2: head h0 k-half 1 -> Qb1
    for (int i = tid; i < 64 * 32; i += 256) {
        int r = i >> 5, c = (i & 31) * 4;
        cp16(&Qb1[r * 132 + c], g_QA[h0] + PROW(r) * ND + 128 + c);
    }
    asm volatile("cp.async.commit_group;");

    unsigned long long zacc[4][8];
    #pragma unroll
    for (int i = 0; i < 4; i++)
        #pragma unroll
        for (int j = 0; j < 8; j++) zacc[i][j] = 0ull;

    for (int t = 0; t < 4; t++) {
        int h = h0 + t;
        unsigned long long acc[4][4];
        #pragma unroll
        for (int i = 0; i < 4; i++)
            #pragma unroll
            for (int j = 0; j < 4; j++) acc[i][j] = 0ull;

        // ---- phase 0: k in [0,128) from Qb0 ----
        asm volatile("cp.async.wait_group 1;");   // Qb0 (and K/V at t=0) ready
        __syncthreads();
        for (int kk = 0; kk < 128; kk += 4) {
            ulonglong2 a[4], bb[4];
            #pragma unroll
            for (int i = 0; i < 4; i++)
                a[i]  = *(const ulonglong2*)&Qb0[(ty + 16 * i) * 132 + kk];
            #pragma unroll
            for (int j = 0; j < 4; j++)
                bb[j] = *(const ulonglong2*)&Ks[(tx + 16 * j) * 260 + kk];
            #pragma unroll
            for (int i = 0; i < 4; i++)
                #pragma unroll
                for (int j = 0; j < 4; j++) {
                    acc[i][j] = ffma2(a[i].x, bb[j].x, acc[i][j]);
                    acc[i][j] = ffma2(a[i].y, bb[j].y, acc[i][j]);
                }
        }
        __syncthreads();   // all threads done with Qb0
        if (t < 3) {       // prefetch head h+1 k-half 0 -> Qb0
            const float* Qn = g_QA[h + 1];
            for (int i = tid; i < 64 * 32; i += 256) {
                int r = i >> 5, c = (i & 31) * 4;
                cp16(&Qb0[r * 132 + c], Qn + PROW(r) * ND + c);
            }
            asm volatile("cp.async.commit_group;");
        }

        // ---- phase 1: k in [128,256) from Qb1 ----
        if (t == 3) asm volatile("cp.async.wait_group 0;");
        else        asm volatile("cp.async.wait_group 1;");
        __syncthreads();
        for (int kk = 0; kk < 128; kk += 4) {
            ulonglong2 a[4], bb[4];
            #pragma unroll
            for (int i = 0; i < 4; i++)
                a[i]  = *(const ulonglong2*)&Qb1[(ty + 16 * i) * 132 + kk];
            #pragma unroll
            for (int j = 0; j < 4; j++)
                bb[j] = *(const ulonglong2*)&Ks[(tx + 16 * j) * 260 + 128 + kk];
            #pragma unroll
            for (int i = 0; i < 4; i++)
                #pragma unroll
                for (int j = 0; j < 4; j++) {
                    acc[i][j] = ffma2(a[i].x, bb[j].x, acc[i][j]);
                    acc[i][j] = ffma2(a[i].y, bb[j].y, acc[i][j]);
                }
        }
        #pragma unroll
        for (int i = 0; i < 4; i++)
            #pragma unroll
            for (int j = 0; j < 4; j++) {
                float2 f = unpack2(acc[i][j]);
                Ss[(ty + 16 * i) * 68 + tx + 16 * j] = f.x + f.y;
            }
        __syncthreads();   // Qb1 free; Ss visible
        if (t < 3) {       // prefetch head h+1 k-half 1 -> Qb1
            const float* Qn = g_QA[h + 1];
            for (int i = tid; i < 64 * 32; i += 256) {
                int r = i >> 5, c = (i & 31) * 4;
                cp16(&Qb1[r * 132 + c], Qn + PROW(r) * ND + 128 + c);
            }
            asm volatile("cp.async.commit_group;");
        }

        // ---- softmax over z (row-wise), 8 warps x 8 rows ----
        {
            int lane = tid & 31, w = tid >> 5;
            #pragma unroll
            for (int rr = 0; rr < 8; rr++) {
                int row = w * 8 + rr;
                float v0 = Ss[row * 68 + lane];
                float v1 = Ss[row * 68 + lane + 32];
                float m = fmaxf(v0, v1);
                #pragma unroll
                for (int off = 16; off > 0; off >>= 1)
                    m = fmaxf(m, __shfl_xor_sync(0xffffffffu, m, off));
                float e0 = __expf(v0 - m), e1 = __expf(v1 - m);
                float s = e0 + e1;
                #pragma unroll
                for (int off = 16; off > 0; off >>= 1)
                    s += __shfl_xor_sync(0xffffffffu, s, off);
                float inv = 1.0f / s;
                Ss[row * 68 + lane]      = e0 * inv;
                Ss[row * 68 + lane + 32] = e1 * inv;
            }
        }
        __syncthreads();

        // ---- O-phase: 4 rows x 16 cols, folded into zacc with ow_h ----
        unsigned long long oacc[4][8];
        #pragma unroll
        for (int i = 0; i < 4; i++)
            #pragma unroll
            for (int j = 0; j < 8; j++) oacc[i][j] = 0ull;
        #pragma unroll 4
        for (int z = 0; z < 64; z++) {
            unsigned long long b2[8];
            #pragma unroll
            for (int j = 0; j < 4; j++) {
                ulonglong2 tv = *(const ulonglong2*)&Vs[z * 260 + tx * 4 + 64 * j];
                b2[2 * j] = tv.x; b2[2 * j + 1] = tv.y;
            }
            #pragma unroll
            for (int i = 0; i < 4; i++) {
                unsigned long long ab = bcast2(Ss[(ty + 16 * i) * 68 + z]);
                #pragma unroll
                for (int j = 0; j < 8; j++)
                    oacc[i][j] = ffma2(ab, b2[j], oacc[i][j]);
            }
        }
        #pragma unroll
        for (int j = 0; j < 4; j++) {
            ulonglong2 w2 = *(const ulonglong2*)&ows[t * 256 + tx * 4 + 64 * j];
            #pragma unroll
            for (int i = 0; i < 4; i++) {
                zacc[i][2 * j]     = ffma2(oacc[i][2 * j],     w2.x, zacc[i][2 * j]);
                zacc[i][2 * j + 1] = ffma2(oacc[i][2 * j + 1], w2.y, zacc[i][2 * j + 1]);
            }
        }
    }

    float* Zp = g_Zp[mode];
    #pragma unroll
    for (int i = 0; i < 4; i++) {
        int r = ty + 16 * i;
        size_t row = PROW(r);
        #pragma unroll
        for (int j = 0; j < 4; j++) {
            float2 lo = unpack2(zacc[i][2 * j]);
            float2 hi = unpack2(zacc[i][2 * j + 1]);
            *(float4*)(Zp + row * ND + tx * 4 + 64 * j) = make_float4(lo.x, lo.y, hi.x, hi.y);
        }
    }
    #undef PROW
}

// ---------------------------------------------------------------------------
// out = Zp0 + Zp1 (pure streaming add)
__global__ void zfinal_kernel(float* __restrict__ out) {
    size_t i = ((size_t)blockIdx.x * 256 + threadIdx.x) * 4;
    float4 a = *(const float4*)(g_Zp[0] + i);
    float4 b = *(const float4*)(g_Zp[1] + i);
    *(float4*)(out + i) = make_float4(a.x + b.x, a.y + b.y, a.z + b.z, a.w + b.w);
}

// ---------------------------------------------------------------------------
extern "C" void kernel_launch(void* const* d_in, const int* in_sizes, int n_in,
                              void* d_out, int out_size) {
    const float* x  = (const float*)d_in[0];
    const float* q  = (const float*)d_in[1];
    const float* km = (const float*)d_in[2];
    const float* v  = (const float*)d_in[3];
    const float* o  = (const float*)d_in[4];
    float* out = (float*)d_out;

    const size_t attn_smem =
        (size_t)(2 * 16640 + 2 * 8448 + 4352 + 1024) * sizeof(float); // 223616 B
    cudaFuncSetAttribute(attn_kernel, cudaFuncAttributeMaxDynamicSharedMemorySize,
                         (int)attn_smem);
    const size_t gemm_smem = (size_t)(33280 + 2 * 8320) * sizeof(float); // 199680 B
    cudaFuncSetAttribute(gemm_xw_kernel, cudaFuncAttributeMaxDynamicSharedMemorySize,
                         (int)gemm_smem);

    prep_ow_kernel<<<NH, ND>>>(o);
    prep_A_kernel<<<dim3(4, 4, 8), 256>>>(q, km);
    gemm_xw_kernel<<<dim3(9, NR / 128), 256, gemm_smem>>>(x, v);
    attn_kernel<<<2 * NB * NN, 256, attn_smem>>>(x);
    zfinal_kernel<<<(NR * ND) / (256 * 4), 256>>>(out);
}

// round 12
// speedup vs baseline: 1.0540x; 1.0003x over previous
#include <cuda_runtime.h>
#include <math.h>

#define NB 8
#define NM 64
#define NN 64
#define ND 256
#define NH 8
#define NR (NB*NM*NN)   // 32768 rows

// Scratch
__device__ float g_QA[9][(size_t)NR * ND];   // 0..7: Q-proj per head, 8: V = x@v
__device__ float g_Zp[2][(size_t)NR * ND];   // per-mode partial Z
__device__ float g_A[8][ND * ND];            // A_h = q_h @ k^T
__device__ float g_ow[NH * ND];              // ow[h,d] = sum_v o[h,d,v]

// ---------------------------------------------------------------------------
// packed f32x2 helpers (sm_100+): 2 MACs per fma-pipe issue slot
__device__ __forceinline__ unsigned long long ffma2(unsigned long long a,
                                                    unsigned long long b,
                                                    unsigned long long c) {
    unsigned long long d;
    asm("fma.rn.f32x2 %0, %1, %2, %3;" : "=l"(d) : "l"(a), "l"(b), "l"(c));
    return d;
}
__device__ __forceinline__ unsigned long long bcast2(float a) {
    unsigned long long d;
    asm("mov.b64 %0, {%1, %1};" : "=l"(d) : "f"(a));
    return d;
}
__device__ __forceinline__ float2 unpack2(unsigned long long a) {
    float2 f;
    asm("mov.b64 {%0, %1}, %2;" : "=f"(f.x), "=f"(f.y) : "l"(a));
    return f;
}
__device__ __forceinline__ void cp16(float* dst_smem, const float* src) {
    unsigned s = (unsigned)__cvta_generic_to_shared(dst_smem);
    asm volatile("cp.async.cg.shared.global [%0], [%1], 16;" :: "r"(s), "l"(src));
}

// ---------------------------------------------------------------------------
__global__ void prep_ow_kernel(const float* __restrict__ o) {
    int h = blockIdx.x;
    int d = threadIdx.x;
    const float* row = o + ((size_t)h * ND + d) * ND;
    float s = 0.f;
    #pragma unroll 8
    for (int v = 0; v < ND; v++) s += row[v];
    g_ow[h * ND + d] = s;
}

// ---------------------------------------------------------------------------
// A_h[d][e] = sum_k q[h][d][k] * kmat[e][k]
__global__ void __launch_bounds__(256) prep_A_kernel(const float* __restrict__ q,
                                                     const float* __restrict__ kmat) {
    __shared__ float Qs[64 * 68];
    __shared__ float Ks[64 * 68];
    int h  = blockIdx.z;
    int d0 = blockIdx.y * 64;
    int e0 = blockIdx.x * 64;
    int tid = threadIdx.x, ty = tid >> 4, tx = tid & 15;
    const float* qh = q + (size_t)h * ND * ND;
    unsigned long long acc[4][4];
    #pragma unroll
    for (int i = 0; i < 4; i++)
        #pragma unroll
        for (int j = 0; j < 4; j++) acc[i][j] = 0ull;
    for (int kc = 0; kc < ND; kc += 64) {
        __syncthreads();
        #pragma unroll
        for (int i = tid; i < 64 * 16; i += 256) {
            int r = i >> 4, c = (i & 15) * 4;
            *(float4*)&Qs[r * 68 + c] = *(const float4*)(qh   + (size_t)(d0 + r) * ND + kc + c);
            *(float4*)&Ks[r * 68 + c] = *(const float4*)(kmat + (size_t)(e0 + r) * ND + kc + c);
        }
        __syncthreads();
        for (int kk = 0; kk < 64; kk += 4) {
            ulonglong2 a[4], b[4];
            #pragma unroll
            for (int i = 0; i < 4; i++)
                a[i] = *(const ulonglong2*)&Qs[(ty + 16 * i) * 68 + kk];
            #pragma unroll
            for (int j = 0; j < 4; j++)
                b[j] = *(const ulonglong2*)&Ks[(tx + 16 * j) * 68 + kk];
            #pragma unroll
            for (int i = 0; i < 4; i++)
                #pragma unroll
                for (int j = 0; j < 4; j++) {
                    acc[i][j] = ffma2(a[i].x, b[j].x, acc[i][j]);
                    acc[i][j] = ffma2(a[i].y, b[j].y, acc[i][j]);
                }
        }
    }
    #pragma unroll
    for (int i = 0; i < 4; i++)
        #pragma unroll
        for (int j = 0; j < 4; j++) {
            float2 f = unpack2(acc[i][j]);
            g_A[h][(size_t)(d0 + ty + 16 * i) * ND + e0 + tx + 16 * j] = f.x + f.y;
        }
}

// ---------------------------------------------------------------------------
// For hz<8: g_QA[hz] = X @ g_A[hz]; hz==8: g_QA[8] = X @ v
// 128-row M-tile, 256 threads, 8x16 per-thread tile (0.75 B/MAC).
// X panel staged ONCE at full k (128 x 260); W double-buffered per 32-k chunk.
__global__ void __launch_bounds__(256, 1) gemm_xw_kernel(const float* __restrict__ x,
                                                         const float* __restrict__ vin) {
    extern __shared__ float smg[];
    float* Xs  = smg;                     // 128 x 260 = 33280 floats
    float* Ws0 = smg + 33280;             // 32 x 260  = 8320
    float* Ws1 = smg + 33280 + 8320;      // 32 x 260  = 8320

    int hz = blockIdx.x;
    const float* W = (hz < 8) ? g_A[hz] : vin;
    float* C = g_QA[hz];
    size_t r0 = (size_t)blockIdx.y * 128;
    int tid = threadIdx.x, ty = tid >> 4, tx = tid & 15;   // ty 0..15, tx 0..15

    unsigned long long acc[8][8];
    #pragma unroll
    for (int i = 0; i < 8; i++)
        #pragma unroll
        for (int j = 0; j < 8; j++) acc[i][j] = 0ull;

    // group 0: full X panel + W chunk 0
    for (int i = tid; i < 128 * 64; i += 256) {
        int r = i >> 6, c = (i & 63) * 4;
        cp16(&Xs[r * 260 + c], x + (r0 + r) * ND + c);
    }
    #pragma unroll
    for (int i = tid; i < 32 * 64; i += 256) {
        int r = i >> 6, c = (i & 63) * 4;
        cp16(&Ws0[r * 260 + c], W + (size_t)r * ND + c);
    }
    asm volatile("cp.async.commit_group;");

    for (int ch = 0; ch < 8; ch++) {
        if (ch + 1 < 8) {
            int dc = (ch + 1) * 32;
            float* Wd = (ch + 1) & 1 ? Ws1 : Ws0;
            #pragma unroll
            for (int i = tid; i < 32 * 64; i += 256) {
                int r = i >> 6, c = (i & 63) * 4;
                cp16(&Wd[r * 260 + c], W + (size_t)(dc + r) * ND + c);
            }
            asm volatile("cp.async.commit_group;");
            asm volatile("cp.async.wait_group 1;");
        } else {
            asm volatile("cp.async.wait_group 0;");
        }
        __syncthreads();

        const float* Ws = (ch & 1) ? Ws1 : Ws0;
        int base = ch * 32;
        #pragma unroll 4
        for (int kk = 0; kk < 32; kk += 4) {
            float a4[8][4];
            #pragma unroll
            for (int i = 0; i < 8; i++)
                *(float4*)a4[i] = *(const float4*)&Xs[(ty + 16 * i) * 260 + base + kk];
            #pragma unroll
            for (int q = 0; q < 4; q++) {
                unsigned long long b2[8];
                #pragma unroll
                for (int j = 0; j < 4; j++) {
                    ulonglong2 t = *(const ulonglong2*)&Ws[(kk + q) * 260 + tx * 4 + 64 * j];
                    b2[2 * j] = t.x; b2[2 * j + 1] = t.y;
                }
                #pragma unroll
                for (int i = 0; i < 8; i++) {
                    unsigned long long ab = bcast2(a4[i][q]);
                    #pragma unroll
                    for (int j = 0; j < 8; j++)
                        acc[i][j] = ffma2(ab, b2[j], acc[i][j]);
                }
            }
        }
        __syncthreads();   // done with this W buffer before it's refilled
    }

    #pragma unroll
    for (int i = 0; i < 8; i++) {
        size_t row = r0 + ty + 16 * i;
        #pragma unroll
        for (int j = 0; j < 4; j++) {
            float2 lo = unpack2(acc[i][2 * j]);
            float2 hi = unpack2(acc[i][2 * j + 1]);
            *(float4*)(C + row * ND + tx * 4 + 64 * j) = make_float4(lo.x, lo.y, hi.x, hi.y);
        }
    }
}

// ---------------------------------------------------------------------------
// Fused attention + output projection, cp.async-pipelined QA staging.
// QA arrives in k-half panels (64 rows x 128 k): Qb0 = k[0,128), Qb1 = k[128,256).
// Logits accumulate across both phases; K tile loaded ONCE per k (2 B/MAC).
//   mode 0: attn over m (panel p = n), heads 0..3.
//   mode 1: attn over n (panel p = m), heads 4..7.   (round-9 proven)
__global__ void __launch_bounds__(256, 1) attn_kernel(const float* __restrict__ x) {
    extern __shared__ float sm[];
    float* Ks  = sm;                        // 64 x 260 = 16640
    float* Vs  = sm + 16640;                // 64 x 260 = 16640
    float* Qb0 = sm + 2 * 16640;            // 64 x 132 = 8448  (k-half 0)
    float* Qb1 = sm + 2 * 16640 + 8448;     // 64 x 132 = 8448  (k-half 1)
    float* Ss  = sm + 2 * 16640 + 2 * 8448; // 64 x 68  = 4352
    float* ows = Ss + 4352;                 // 4 x 256  = 1024

    int mode = blockIdx.x >> 9;
    int idx  = blockIdx.x & 511;
    int b = idx >> 6;
    int p = idx & 63;
    int tid = threadIdx.x, ty = tid >> 4, tx = tid & 15;
    size_t base = (size_t)b * NM * NN;
    const float* Vg = g_QA[8];
    int h0 = mode ? 4 : 0;

    #define PROW(r) (base + (mode ? ((size_t)p * 64 + (r)) : ((size_t)(r) * 64 + p)))

    // group 0: K, V, ows
    for (int i = tid; i < 64 * 64; i += 256) {
        int r = i >> 6, c = (i & 63) * 4;
        cp16(&Ks[r * 260 + c], x + PROW(r) * ND + c);
    }
    for (int i = tid; i < 64 * 64; i += 256) {
        int r = i >> 6, c = (i & 63) * 4;
        cp16(&Vs[r * 260 + c], Vg + PROW(r) * ND + c);
    }
    {
        int hh = tid >> 6, c = (tid & 63) * 4;
        cp16(&ows[hh * 256 + c], g_ow + (h0 + hh) * ND + c);
    }
    asm volatile("cp.async.commit_group;");
    // group 1: head h0 k-half 0 -> Qb0
    for (int i = tid; i < 64 * 32; i += 256) {
        int r = i >> 5, c = (i & 31) * 4;
        cp16(&Qb0[r * 132 + c], g_QA[h0] + PROW(r) * ND + c);
    }
    asm volatile("cp.async.commit_group;");
    // group 2: head h0 k-half 1 -> Qb1
    for (int i = tid; i < 64 * 32; i += 256) {
        int r = i >> 5, c = (i & 31) * 4;
        cp16(&Qb1[r * 132 + c], g_QA[h0] + PROW(r) * ND + 128 + c);
    }
    asm volatile("cp.async.commit_group;");

    unsigned long long zacc[4][8];
    #pragma unroll
    for (int i = 0; i < 4; i++)
        #pragma unroll
        for (int j = 0; j < 8; j++) zacc[i][j] = 0ull;

    for (int t = 0; t < 4; t++) {
        int h = h0 + t;
        unsigned long long acc[4][4];
        #pragma unroll
        for (int i = 0; i < 4; i++)
            #pragma unroll
            for (int j = 0; j < 4; j++) acc[i][j] = 0ull;

        // ---- phase 0: k in [0,128) from Qb0 ----
        asm volatile("cp.async.wait_group 1;");   // Qb0 (and K/V at t=0) ready
        __syncthreads();
        for (int kk = 0; kk < 128; kk += 4) {
            ulonglong2 a[4], bb[4];
            #pragma unroll
            for (int i = 0; i < 4; i++)
                a[i]  = *(const ulonglong2*)&Qb0[(ty + 16 * i) * 132 + kk];
            #pragma unroll
            for (int j = 0; j < 4; j++)
                bb[j] = *(const ulonglong2*)&Ks[(tx + 16 * j) * 260 + kk];
            #pragma unroll
            for (int i = 0; i < 4; i++)
                #pragma unroll
                for (int j = 0; j < 4; j++) {
                    acc[i][j] = ffma2(a[i].x, bb[j].x, acc[i][j]);
                    acc[i][j] = ffma2(a[i].y, bb[j].y, acc[i][j]);
                }
        }
        __syncthreads();   // all threads done with Qb0
        if (t < 3) {       // prefetch head h+1 k-half 0 -> Qb0
            const float* Qn = g_QA[h + 1];
            for (int i = tid; i < 64 * 32; i += 256) {
                int r = i >> 5, c = (i & 31) * 4;
                cp16(&Qb0[r * 132 + c], Qn + PROW(r) * ND + c);
            }
            asm volatile("cp.async.commit_group;");
        }

        // ---- phase 1: k in [128,256) from Qb1 ----
        if (t == 3) asm volatile("cp.async.wait_group 0;");
        else        asm volatile("cp.async.wait_group 1;");
        __syncthreads();
        for (int kk = 0; kk < 128; kk += 4) {
            ulonglong2 a[4], bb[4];
            #pragma unroll
            for (int i = 0; i < 4; i++)
                a[i]  = *(const ulonglong2*)&Qb1[(ty + 16 * i) * 132 + kk];
            #pragma unroll
            for (int j = 0; j < 4; j++)
                bb[j] = *(const ulonglong2*)&Ks[(tx + 16 * j) * 260 + 128 + kk];
            #pragma unroll
            for (int i = 0; i < 4; i++)
                #pragma unroll
                for (int j = 0; j < 4; j++) {
                    acc[i][j] = ffma2(a[i].x, bb[j].x, acc[i][j]);
                    acc[i][j] = ffma2(a[i].y, bb[j].y, acc[i][j]);
                }
        }
        #pragma unroll
        for (int i = 0; i < 4; i++)
            #pragma unroll
            for (int j = 0; j < 4; j++) {
                float2 f = unpack2(acc[i][j]);
                Ss[(ty + 16 * i) * 68 + tx + 16 * j] = f.x + f.y;
            }
        __syncthreads();   // Qb1 free; Ss visible
        if (t < 3) {       // prefetch head h+1 k-half 1 -> Qb1
            const float* Qn = g_QA[h + 1];
            for (int i = tid; i < 64 * 32; i += 256) {
                int r = i >> 5, c = (i & 31) * 4;
                cp16(&Qb1[r * 132 + c], Qn + PROW(r) * ND + 128 + c);
            }
            asm volatile("cp.async.commit_group;");
        }

        // ---- softmax over z (row-wise), 8 warps x 8 rows ----
        {
            int lane = tid & 31, w = tid >> 5;
            #pragma unroll
            for (int rr = 0; rr < 8; rr++) {
                int row = w * 8 + rr;
                float v0 = Ss[row * 68 + lane];
                float v1 = Ss[row * 68 + lane + 32];
                float m = fmaxf(v0, v1);
                #pragma unroll
                for (int off = 16; off > 0; off >>= 1)
                    m = fmaxf(m, __shfl_xor_sync(0xffffffffu, m, off));
                float e0 = __expf(v0 - m), e1 = __expf(v1 - m);
                float s = e0 + e1;
                #pragma unroll
                for (int off = 16; off > 0; off >>= 1)
                    s += __shfl_xor_sync(0xffffffffu, s, off);
                float inv = 1.0f / s;
                Ss[row * 68 + lane]      = e0 * inv;
                Ss[row * 68 + lane + 32] = e1 * inv;
            }
        }
        __syncthreads();

        // ---- O-phase: 4 rows x 16 cols, folded into zacc with ow_h ----
        unsigned long long oacc[4][8];
        #pragma unroll
        for (int i = 0; i < 4; i++)
            #pragma unroll
            for (int j = 0; j < 8; j++) oacc[i][j] = 0ull;
        #pragma unroll 4
        for (int z = 0; z < 64; z++) {
            unsigned long long b2[8];
            #pragma unroll
            for (int j = 0; j < 4; j++) {
                ulonglong2 tv = *(const ulonglong2*)&Vs[z * 260 + tx * 4 + 64 * j];
                b2[2 * j] = tv.x; b2[2 * j + 1] = tv.y;
            }
            #pragma unroll
            for (int i = 0; i < 4; i++) {
                unsigned long long ab = bcast2(Ss[(ty + 16 * i) * 68 + z]);
                #pragma unroll
                for (int j = 0; j < 8; j++)
                    oacc[i][j] = ffma2(ab, b2[j], oacc[i][j]);
            }
        }
        #pragma unroll
        for (int j = 0; j < 4; j++) {
            ulonglong2 w2 = *(const ulonglong2*)&ows[t * 256 + tx * 4 + 64 * j];
            #pragma unroll
            for (int i = 0; i < 4; i++) {
                zacc[i][2 * j]     = ffma2(oacc[i][2 * j],     w2.x, zacc[i][2 * j]);
                zacc[i][2 * j + 1] = ffma2(oacc[i][2 * j + 1], w2.y, zacc[i][2 * j + 1]);
            }
        }
    }

    float* Zp = g_Zp[mode];
    #pragma unroll
    for (int i = 0; i < 4; i++) {
        int r = ty + 16 * i;
        size_t row = PROW(r);
        #pragma unroll
        for (int j = 0; j < 4; j++) {
            float2 lo = unpack2(zacc[i][2 * j]);
            float2 hi = unpack2(zacc[i][2 * j + 1]);
            *(float4*)(Zp + row * ND + tx * 4 + 64 * j) = make_float4(lo.x, lo.y, hi.x, hi.y);
        }
    }
    #undef PROW
}

// ---------------------------------------------------------------------------
// out = Zp0 + Zp1 (pure streaming add)
__global__ void zfinal_kernel(float* __restrict__ out) {
    size_t i = ((size_t)blockIdx.x * 256 + threadIdx.x) * 4;
    float4 a = *(const float4*)(g_Zp[0] + i);
    float4 b = *(const float4*)(g_Zp[1] + i);
    *(float4*)(out + i) = make_float4(a.x + b.x, a.y + b.y, a.z + b.z, a.w + b.w);
}

// ---------------------------------------------------------------------------
extern "C" void kernel_launch(void* const* d_in, const int* in_sizes, int n_in,
                              void* d_out, int out_size) {
    const float* x  = (const float*)d_in[0];
    const float* q  = (const float*)d_in[1];
    const float* km = (const float*)d_in[2];
    const float* v  = (const float*)d_in[3];
    const float* o  = (const float*)d_in[4];
    float* out = (float*)d_out;

    const size_t attn_smem =
        (size_t)(2 * 16640 + 2 * 8448 + 4352 + 1024) * sizeof(float); // 223616 B
    cudaFuncSetAttribute(attn_kernel, cudaFuncAttributeMaxDynamicSharedMemorySize,
                         (int)attn_smem);
    const size_t gemm_smem = (size_t)(33280 + 2 * 8320) * sizeof(float); // 199680 B
    cudaFuncSetAttribute(gemm_xw_kernel, cudaFuncAttributeMaxDynamicSharedMemorySize,
                         (int)gemm_smem);

    prep_ow_kernel<<<NH, ND>>>(o);
    prep_A_kernel<<<dim3(4, 4, 8), 256>>>(q, km);
    gemm_xw_kernel<<<dim3(9, NR / 128), 256, gemm_smem>>>(x, v);
    attn_kernel<<<2 * NB * NN, 256, attn_smem>>>(x);
    zfinal_kernel<<<(NR * ND) / (256 * 4), 256>>>(out);
}